// round 10
// baseline (speedup 1.0000x reference)
#include <cuda_runtime.h>
#include <cstddef>
#include <cstdint>

// ---------------- problem constants ----------------
constexpr int B      = 2;
constexpr int C      = 256;
constexpr int H      = 256;
constexpr int W      = 256;
constexpr int NROI   = 1000;
constexpr int PH     = 7;
constexpr int PW     = 7;
constexpr int OUT    = 1024;
constexpr int NCLS   = 11;    // NUM_CLASSES + 1
constexpr int NREG   = 5;
constexpr int D      = C * PH * PW;   // 12544
constexpr int M      = B * NROI;      // 2000
constexpr int HW     = H * W;
constexpr int NSAMP  = PH * PW * 4;   // 196

// ---------------- scratch (static device globals; no allocation) ----------------
__device__ float g_feat_t[(size_t)B * HW * C];   // [B, H, W, C]
__device__ float g_x[(size_t)M * D];             // aligned features (tf32-rounded)
__device__ float g_w1t[(size_t)OUT * D];         // w1 transposed [N,K] (tf32-rounded)
__device__ float g_w2t[(size_t)OUT * OUT];       // w2 transposed
__device__ float g_h1[(size_t)M * OUT];
__device__ float g_h2[(size_t)M * OUT];

// ---------------- helpers ----------------
__device__ __forceinline__ uint32_t smem_u32(const void* p) {
    uint32_t a;
    asm("{ .reg .u64 t; cvta.to.shared.u64 t, %1; cvt.u32.u64 %0, t; }" : "=r"(a) : "l"(p));
    return a;
}
__device__ __forceinline__ float tf32_round(float x) {
    uint32_t u;
    asm("cvt.rna.tf32.f32 %0, %1;" : "=r"(u) : "f"(x));
    return __uint_as_float(u);
}
__device__ __forceinline__ void cpasync16(uint32_t s, const void* g, bool pred) {
    int sz = pred ? 16 : 0;
    asm volatile("cp.async.cg.shared.global [%0], [%1], 16, %2;"
                 :: "r"(s), "l"(g), "r"(sz) : "memory");
}
__device__ __forceinline__ void cp_commit() {
    asm volatile("cp.async.commit_group;" ::: "memory");
}
__device__ __forceinline__ void cp_wait2() {
    asm volatile("cp.async.wait_group 2;" ::: "memory");
}
__device__ __forceinline__ void mma_tf32(float* d, const uint32_t* a, uint32_t b0, uint32_t b1) {
    asm volatile(
        "mma.sync.aligned.m16n8k8.row.col.f32.tf32.tf32.f32 "
        "{%0,%1,%2,%3}, {%4,%5,%6,%7}, {%8,%9}, {%0,%1,%2,%3};"
        : "+f"(d[0]), "+f"(d[1]), "+f"(d[2]), "+f"(d[3])
        : "r"(a[0]), "r"(a[1]), "r"(a[2]), "r"(a[3]), "r"(b0), "r"(b1));
}
__device__ __forceinline__ void ldsm4(uint32_t* r, uint32_t addr) {
    asm volatile("ldmatrix.sync.aligned.m8n8.x4.shared.b16 {%0,%1,%2,%3}, [%4];"
        : "=r"(r[0]), "=r"(r[1]), "=r"(r[2]), "=r"(r[3]) : "r"(addr));
}

// ---------------- 1. generic 32x32 transpose: in[z][R][Cc] -> out[z][Cc][R] ----------------
__global__ void transpose_kernel(const float* __restrict__ in, float* __restrict__ out,
                                 int R, int Cc, int doRound) {
    __shared__ float tile[32][33];
    size_t zo = (size_t)blockIdx.z * R * Cc;
    int c0 = blockIdx.x * 32;
    int r0 = blockIdx.y * 32;
    int tx = threadIdx.x, ty = threadIdx.y;
    #pragma unroll
    for (int i = 0; i < 32; i += 8)
        tile[ty + i][tx] = in[zo + (size_t)(r0 + ty + i) * Cc + c0 + tx];
    __syncthreads();
    #pragma unroll
    for (int i = 0; i < 32; i += 8) {
        float v = tile[tx][ty + i];
        if (doRound) v = tf32_round(v);
        out[zo + (size_t)(c0 + ty + i) * R + r0 + tx] = v;
    }
}

// ---------------- 2. rotated RoI align: geometry + float2 gather, bin-split ----------------
constexpr int ROI_SMEM = D * 4 + NSAMP * 32;   // 56448 B

__global__ void __launch_bounds__(256) roi_align_kernel(const float* __restrict__ rois) {
    extern __shared__ float sacc[];                       // [D]
    uint4*  soff = (uint4*)(sacc + D);                    // [NSAMP]
    float4* swt  = (float4*)(soff + NSAMP);               // [NSAMP]

    int m = blockIdx.x;
    int b = m / NROI;
    int tid = threadIdx.x;

    // ---- Phase A: geometry, 196 samples on first 196 threads ----
    if (tid < NSAMP) {
        const float* rp = rois + (size_t)m * 5;
        float cx = rp[0], cy = rp[1], w = rp[2], h = rp[3], th = rp[4];
        float cosT = cosf(th), sinT = sinf(th);
        float bin_h = h * (1.0f / PH);
        float bin_w = w * (1.0f / PW);

        int bin = tid >> 2;          // 0..48
        int sub = tid & 3;           // 0..3
        int ph  = bin / PW;
        int pw  = bin % PW;
        int sy  = sub >> 1;
        int sx  = sub & 1;

        float yy = -h * 0.5f + ((float)ph + (sy + 0.5f) * 0.5f) * bin_h;
        float xx = -w * 0.5f + ((float)pw + (sx + 0.5f) * 0.5f) * bin_w;
        float xs = cx + xx * cosT - yy * sinT;
        float ys = cy + xx * sinT + yy * cosT;
        bool valid = (ys > -1.0f) && (ys < (float)H) &&
                     (xs > -1.0f) && (xs < (float)W);
        float y = fminf(fmaxf(ys, 0.0f), (float)(H - 1));
        float x = fminf(fmaxf(xs, 0.0f), (float)(W - 1));
        int y0 = (int)floorf(y);
        int x0 = (int)floorf(x);
        int y1 = min(y0 + 1, H - 1);
        int x1 = min(x0 + 1, W - 1);
        float ly = y - (float)y0, lx = x - (float)x0;
        float hy = 1.0f - ly,     hx = 1.0f - lx;

        float sc = valid ? 0.25f : 0.0f;    // fold subsample mean + validity
        uint32_t r0 = (uint32_t)(y0 * W) * (uint32_t)C;
        uint32_t r1 = (uint32_t)(y1 * W) * (uint32_t)C;
        uint32_t c0 = (uint32_t)x0 * (uint32_t)C;
        uint32_t c1 = (uint32_t)x1 * (uint32_t)C;
        soff[tid] = make_uint4(r0 + c0, r0 + c1, r1 + c0, r1 + c1);
        swt[tid]  = make_float4(hy * hx * sc, hy * lx * sc, ly * hx * sc, ly * lx * sc);
    }
    __syncthreads();

    // ---- Phase B: 2 channels/thread, bins split across half-blocks ----
    int half = tid >> 7;                 // 0 or 1
    int c = (tid & 127) * 2;
    int bin0 = half ? 25 : 0;
    int bin1 = half ? 49 : 25;
    const float* fb = g_feat_t + (size_t)b * HW * C + c;   // even offset -> 8B aligned

    #pragma unroll 1
    for (int bin = bin0; bin < bin1; bin++) {
        float ax = 0.0f, ay = 0.0f;
        #pragma unroll
        for (int sub = 0; sub < 4; sub++) {
            int s = bin * 4 + sub;
            uint4  o = soff[s];
            float4 wv = swt[s];
            float2 v00 = __ldg((const float2*)(fb + o.x));
            float2 v01 = __ldg((const float2*)(fb + o.y));
            float2 v10 = __ldg((const float2*)(fb + o.z));
            float2 v11 = __ldg((const float2*)(fb + o.w));
            ax += wv.x * v00.x + wv.y * v01.x + wv.z * v10.x + wv.w * v11.x;
            ay += wv.x * v00.y + wv.y * v01.y + wv.z * v10.y + wv.w * v11.y;
        }
        sacc[c * (PH * PW) + bin]       = ax;
        sacc[(c + 1) * (PH * PW) + bin] = ay;
    }
    __syncthreads();

    // ---- coalesced tf32-rounded writeout (float4 granularity) ----
    float* outrow = g_x + (size_t)m * D;
    for (int i = tid * 4; i < D; i += 256 * 4) {
        float4 v = *(const float4*)(sacc + i);
        v.x = tf32_round(v.x); v.y = tf32_round(v.y);
        v.z = tf32_round(v.z); v.w = tf32_round(v.w);
        *(float4*)(outrow + i) = v;
    }
}

// ---------------- 3. TF32 mma.sync GEMM with ldmatrix fragment loads ----------------
// C[M,1024] = A[M,K] @ Bt[1024,K]^T
// 128x128 CTA tile, BK=32, 8 warps (2x4), warp tile 64x32, 4-stage cp.async.
constexpr int SSTR   = 36;                 // smem row stride (floats), conflict-free
constexpr int STG_F  = 2 * 128 * SSTR;     // floats per stage (As + Bs)
constexpr int NSTG   = 4;
constexpr int SMEM_GEMM = NSTG * STG_F * 4;  // 147456 B

__global__ void __launch_bounds__(256) gemm_tf32_kernel(
    const float* __restrict__ A, const float* __restrict__ Bt,
    const float* __restrict__ bias, float* __restrict__ Cout,
    int Mi, int Ki, int flags)          // flags: bit0 relu, bit1 tf32-round output
{
    extern __shared__ float sm[];
    int tid  = threadIdx.x;
    int wid  = tid >> 5, lane = tid & 31;
    int gq   = lane >> 2;      // groupID 0..7
    int tq   = lane & 3;       // thread-in-group 0..3
    int wm   = wid >> 2;       // 0..1  (m)
    int wn   = wid & 3;        // 0..3  (n)
    int bm   = blockIdx.y * 128;
    int bn   = blockIdx.x * 128;

    // cp.async assignments: 2 threads per row, 4x16B each
    int ldRow  = tid >> 1;
    int ldColF = (tid & 1) * 16;
    int gmA    = bm + ldRow;
    bool aOk   = gmA < Mi;
    const float* gA = A  + (size_t)gmA * Ki + ldColF;
    const float* gB = Bt + (size_t)(bn + ldRow) * Ki + ldColF;
    uint32_t sbase = smem_u32(sm);
    uint32_t sA = sbase + (uint32_t)(ldRow * SSTR + ldColF) * 4u;
    uint32_t sB = sA + 128u * SSTR * 4u;

    const int NT = Ki / 32;

    // prologue: tiles 0,1,2
    #pragma unroll
    for (int s = 0; s < 3; s++) {
        uint32_t so = (uint32_t)(s * STG_F) * 4u;
        #pragma unroll
        for (int j = 0; j < 4; j++) {
            cpasync16(sA + so + j * 16u, gA + s * 32 + j * 4, aOk);
            cpasync16(sB + so + j * 16u, gB + s * 32 + j * 4, true);
        }
        cp_commit();
    }

    float acc[4][4][4];
    #pragma unroll
    for (int i = 0; i < 4; i++)
        #pragma unroll
        for (int j = 0; j < 4; j++)
            #pragma unroll
            for (int k = 0; k < 4; k++) acc[i][j][k] = 0.0f;

    int arb = wm * 64;          // warp row base within tile
    int bcb = wn * 32;          // warp col base within tile

    // per-lane ldmatrix address components (element offsets within stage)
    // A x4 (per am): lanes 0-7 rows r..r+7 col k0; 8-15 rows r+8.. col k0;
    //                16-23 rows r.. col k0+4; 24-31 rows r+8.. col k0+4
    uint32_t aRow = (uint32_t)(arb + (lane & 7) + ((lane >> 3) & 1) * 8);
    uint32_t aCol = (uint32_t)((lane >> 4) * 4);
    uint32_t aOff = (aRow * SSTR + aCol) * 4u;              // + am*16*SSTR*4 + k0*4
    // B x4: fragment i = bq i; lanes 8i..8i+7 rows n.. col k0 (or k0+4)
    uint32_t bRow = (uint32_t)(bcb + (lane >> 3) * 8 + (lane & 7));
    uint32_t bOff = (bRow * SSTR) * 4u;                     // + k0*4

    for (int kt = 0; kt < NT; kt++) {
        cp_wait2();
        __syncthreads();

        // issue loads for tile kt+3 into slot (kt+3)%4 (freed at iter kt-1)
        if (kt + 3 < NT) {
            uint32_t so = (uint32_t)(((kt + 3) & 3) * STG_F) * 4u;
            const float* pa = gA + (kt + 3) * 32;
            const float* pb = gB + (kt + 3) * 32;
            #pragma unroll
            for (int j = 0; j < 4; j++) {
                cpasync16(sA + so + j * 16u, pa + j * 4, aOk);
                cpasync16(sB + so + j * 16u, pb + j * 4, true);
            }
        }
        cp_commit();

        uint32_t smA = sbase + (uint32_t)((kt & 3) * STG_F) * 4u;
        uint32_t smB = smA + 128u * SSTR * 4u;

        // fragment double-buffer across ks sub-steps, loaded via ldmatrix
        uint32_t af[2][4][4];    // [buf][am][reg]
        uint32_t bf[2][2][4];    // [buf][k-half reg][bq]

        // load ks=0 fragments
        #pragma unroll
        for (int am = 0; am < 4; am++)
            ldsm4(af[0][am], smA + aOff + (uint32_t)(am * 16 * SSTR) * 4u);
        ldsm4(bf[0][0], smB + bOff);
        ldsm4(bf[0][1], smB + bOff + 16u);    // k0+4 floats = 16 bytes

        #pragma unroll
        for (int ks = 0; ks < 4; ks++) {
            int cur = ks & 1, nxt = cur ^ 1;
            if (ks < 3) {
                uint32_t k0b = (uint32_t)((ks + 1) * 8) * 4u;
                #pragma unroll
                for (int am = 0; am < 4; am++)
                    ldsm4(af[nxt][am], smA + aOff + (uint32_t)(am * 16 * SSTR) * 4u + k0b);
                ldsm4(bf[nxt][0], smB + bOff + k0b);
                ldsm4(bf[nxt][1], smB + bOff + k0b + 16u);
            }
            #pragma unroll
            for (int am = 0; am < 4; am++)
                #pragma unroll
                for (int bq = 0; bq < 4; bq++)
                    mma_tf32(acc[am][bq], af[cur][am], bf[cur][0][bq], bf[cur][1][bq]);
        }
        // no trailing __syncthreads: next iteration's top barrier provides ordering
    }

    // epilogue: bias + relu (+ tf32 round), write float2 pairs
    bool relu = flags & 1, rnd = flags & 2;
    #pragma unroll
    for (int am = 0; am < 4; am++) {
        int r0 = bm + arb + am * 16 + gq;
        #pragma unroll
        for (int bq = 0; bq < 4; bq++) {
            int cidx = bn + bcb + bq * 8 + tq * 2;
            float b0 = bias[cidx], b1 = bias[cidx + 1];
            #pragma unroll
            for (int half = 0; half < 2; half++) {
                int row = r0 + half * 8;
                if (row < Mi) {
                    float a0 = acc[am][bq][half * 2 + 0] + b0;
                    float a1 = acc[am][bq][half * 2 + 1] + b1;
                    if (relu) { a0 = fmaxf(a0, 0.f); a1 = fmaxf(a1, 0.f); }
                    if (rnd)  { a0 = tf32_round(a0); a1 = tf32_round(a1); }
                    float2 v = make_float2(a0, a1);
                    *(float2*)(Cout + (size_t)row * 1024 + cidx) = v;
                }
            }
        }
    }
}

// ---------------- 4. head: cls (11) + reg (5) ----------------
__global__ void __launch_bounds__(128) head_kernel(
    const float* __restrict__ wc, const float* __restrict__ bc,
    const float* __restrict__ wr, const float* __restrict__ br,
    float* __restrict__ out)
{
    int m = blockIdx.x;
    __shared__ float sx[OUT];
    const float* row = g_h2 + (size_t)m * OUT;
    for (int i = threadIdx.x; i < OUT; i += 128) sx[i] = row[i];
    __syncthreads();

    int o = threadIdx.x >> 3;   // 0..15
    int g = threadIdx.x & 7;
    float acc = 0.0f;
    if (o < NCLS) {
        for (int k = g; k < OUT; k += 8) acc += sx[k] * wc[(size_t)k * NCLS + o];
    } else {
        int oo = o - NCLS;
        for (int k = g; k < OUT; k += 8) acc += sx[k] * wr[(size_t)k * NREG + oo];
    }
    acc += __shfl_down_sync(0xffffffffu, acc, 4, 8);
    acc += __shfl_down_sync(0xffffffffu, acc, 2, 8);
    acc += __shfl_down_sync(0xffffffffu, acc, 1, 8);
    if (g == 0) {
        if (o < NCLS) out[(size_t)m * NCLS + o] = acc + bc[o];
        else out[(size_t)M * NCLS + (size_t)m * NREG + (o - NCLS)] = acc + br[o - NCLS];
    }
}

// ---------------- launch ----------------
extern "C" void kernel_launch(void* const* d_in, const int* in_sizes, int n_in,
                              void* d_out, int out_size)
{
    const float* feat = (const float*)d_in[0];
    const float* rois = (const float*)d_in[1];
    const float* w1   = (const float*)d_in[2];
    const float* b1   = (const float*)d_in[3];
    const float* w2   = (const float*)d_in[4];
    const float* b2   = (const float*)d_in[5];
    const float* wc   = (const float*)d_in[6];
    const float* bc   = (const float*)d_in[7];
    const float* wr   = (const float*)d_in[8];
    const float* br   = (const float*)d_in[9];
    float* out = (float*)d_out;

    float *xbuf, *w1t, *w2t, *h1, *h2;
    cudaGetSymbolAddress((void**)&xbuf, g_x);
    cudaGetSymbolAddress((void**)&w1t,  g_w1t);
    cudaGetSymbolAddress((void**)&w2t,  g_w2t);
    cudaGetSymbolAddress((void**)&h1,   g_h1);
    cudaGetSymbolAddress((void**)&h2,   g_h2);
    float* featT;
    cudaGetSymbolAddress((void**)&featT, g_feat_t);

    // 1. transposes: feat [B,C,HW]->[B,HW,C]; w1 [D,OUT]->[OUT,D]; w2 [OUT,OUT]->[OUT,OUT]
    {
        dim3 blk(32, 8);
        transpose_kernel<<<dim3(HW / 32, C / 32, B), blk>>>(feat, featT, C, HW, 0);
        transpose_kernel<<<dim3(OUT / 32, D / 32, 1), blk>>>(w1, w1t, D, OUT, 1);
        transpose_kernel<<<dim3(OUT / 32, OUT / 32, 1), blk>>>(w2, w2t, OUT, OUT, 1);
    }

    // 2. roi align
    {
        cudaFuncSetAttribute(roi_align_kernel,
                             cudaFuncAttributeMaxDynamicSharedMemorySize, ROI_SMEM);
        roi_align_kernel<<<M, 256, ROI_SMEM>>>(rois);
    }

    // 3. fc1 + fc2 on tf32 mma.sync tensor cores
    cudaFuncSetAttribute(gemm_tf32_kernel,
                         cudaFuncAttributeMaxDynamicSharedMemorySize, SMEM_GEMM);
    {
        dim3 grid(OUT / 128, (M + 127) / 128);   // (8, 16)
        gemm_tf32_kernel<<<grid, 256, SMEM_GEMM>>>(xbuf, w1t, b1, h1, M, D, 3);   // relu+round
        gemm_tf32_kernel<<<grid, 256, SMEM_GEMM>>>(h1, w2t, b2, h2, M, OUT, 1);   // relu
    }

    // 4. heads
    head_kernel<<<M, 128>>>(wc, bc, wr, br, out);
}

// round 12
// speedup vs baseline: 1.4633x; 1.4633x over previous
#include <cuda_runtime.h>
#include <cuda_fp16.h>
#include <cstddef>
#include <cstdint>

// ---------------- problem constants ----------------
constexpr int B      = 2;
constexpr int C      = 256;
constexpr int H      = 256;
constexpr int W      = 256;
constexpr int NROI   = 1000;
constexpr int PH     = 7;
constexpr int PW     = 7;
constexpr int OUT    = 1024;
constexpr int NCLS   = 11;    // NUM_CLASSES + 1
constexpr int NREG   = 5;
constexpr int D      = C * PH * PW;   // 12544
constexpr int M      = B * NROI;      // 2000
constexpr int HW     = H * W;
constexpr int NSAMP  = PH * PW * 4;   // 196

// ---------------- scratch (static device globals; no allocation) ----------------
__device__ float  g_feat_t[(size_t)B * HW * C];   // [B, H, W, C]  f32
__device__ __half g_x[(size_t)M * D];             // aligned features (fp16)
__device__ __half g_w1t[(size_t)OUT * D];         // w1 transposed [N,K] fp16
__device__ __half g_w2t[(size_t)OUT * OUT];       // w2 transposed fp16
__device__ __half g_h1[(size_t)M * OUT];          // fc1 output fp16
__device__ float  g_h2[(size_t)M * OUT];          // fc2 output f32

// ---------------- helpers ----------------
__device__ __forceinline__ uint32_t smem_u32(const void* p) {
    uint32_t a;
    asm("{ .reg .u64 t; cvta.to.shared.u64 t, %1; cvt.u32.u64 %0, t; }" : "=r"(a) : "l"(p));
    return a;
}
__device__ __forceinline__ void cpasync16(uint32_t s, const void* g, bool pred) {
    int sz = pred ? 16 : 0;
    asm volatile("cp.async.cg.shared.global [%0], [%1], 16, %2;"
                 :: "r"(s), "l"(g), "r"(sz) : "memory");
}
__device__ __forceinline__ void cp_commit() {
    asm volatile("cp.async.commit_group;" ::: "memory");
}
__device__ __forceinline__ void cp_wait2() {
    asm volatile("cp.async.wait_group 2;" ::: "memory");
}
__device__ __forceinline__ void mma_f16(float* d, const uint32_t* a, uint32_t b0, uint32_t b1) {
    asm volatile(
        "mma.sync.aligned.m16n8k16.row.col.f32.f16.f16.f32 "
        "{%0,%1,%2,%3}, {%4,%5,%6,%7}, {%8,%9}, {%0,%1,%2,%3};"
        : "+f"(d[0]), "+f"(d[1]), "+f"(d[2]), "+f"(d[3])
        : "r"(a[0]), "r"(a[1]), "r"(a[2]), "r"(a[3]), "r"(b0), "r"(b1));
}

// ---------------- 1a. transpose f32->f32: in[z][R][Cc] -> out[z][Cc][R] ----------------
__global__ void transpose_f32(const float* __restrict__ in, float* __restrict__ out,
                              int R, int Cc) {
    __shared__ float tile[32][33];
    size_t zo = (size_t)blockIdx.z * R * Cc;
    int c0 = blockIdx.x * 32;
    int r0 = blockIdx.y * 32;
    int tx = threadIdx.x, ty = threadIdx.y;
    #pragma unroll
    for (int i = 0; i < 32; i += 8)
        tile[ty + i][tx] = in[zo + (size_t)(r0 + ty + i) * Cc + c0 + tx];
    __syncthreads();
    #pragma unroll
    for (int i = 0; i < 32; i += 8)
        out[zo + (size_t)(c0 + ty + i) * R + r0 + tx] = tile[tx][ty + i];
}

// ---------------- 1b. transpose f32->f16 ----------------
__global__ void transpose_f16(const float* __restrict__ in, __half* __restrict__ out,
                              int R, int Cc) {
    __shared__ float tile[32][33];
    int c0 = blockIdx.x * 32;
    int r0 = blockIdx.y * 32;
    int tx = threadIdx.x, ty = threadIdx.y;
    #pragma unroll
    for (int i = 0; i < 32; i += 8)
        tile[ty + i][tx] = in[(size_t)(r0 + ty + i) * Cc + c0 + tx];
    __syncthreads();
    #pragma unroll
    for (int i = 0; i < 32; i += 8)
        out[(size_t)(c0 + ty + i) * R + r0 + tx] = __float2half_rn(tile[tx][ty + i]);
}

// ---------------- 2. rotated RoI align: geometry + float2 gather, bin-split ----------------
constexpr int ROI_SMEM = D * 4 + NSAMP * 32;   // 56448 B

__global__ void __launch_bounds__(256) roi_align_kernel(const float* __restrict__ rois) {
    extern __shared__ float sacc[];                       // [D]
    uint4*  soff = (uint4*)(sacc + D);                    // [NSAMP]
    float4* swt  = (float4*)(soff + NSAMP);               // [NSAMP]

    int m = blockIdx.x;
    int b = m / NROI;
    int tid = threadIdx.x;

    // ---- Phase A: geometry, 196 samples on first 196 threads ----
    if (tid < NSAMP) {
        const float* rp = rois + (size_t)m * 5;
        float cx = rp[0], cy = rp[1], w = rp[2], h = rp[3], th = rp[4];
        float cosT = cosf(th), sinT = sinf(th);
        float bin_h = h * (1.0f / PH);
        float bin_w = w * (1.0f / PW);

        int bin = tid >> 2;          // 0..48
        int sub = tid & 3;           // 0..3
        int ph  = bin / PW;
        int pw  = bin % PW;
        int sy  = sub >> 1;
        int sx  = sub & 1;

        float yy = -h * 0.5f + ((float)ph + (sy + 0.5f) * 0.5f) * bin_h;
        float xx = -w * 0.5f + ((float)pw + (sx + 0.5f) * 0.5f) * bin_w;
        float xs = cx + xx * cosT - yy * sinT;
        float ys = cy + xx * sinT + yy * cosT;
        bool valid = (ys > -1.0f) && (ys < (float)H) &&
                     (xs > -1.0f) && (xs < (float)W);
        float y = fminf(fmaxf(ys, 0.0f), (float)(H - 1));
        float x = fminf(fmaxf(xs, 0.0f), (float)(W - 1));
        int y0 = (int)floorf(y);
        int x0 = (int)floorf(x);
        int y1 = min(y0 + 1, H - 1);
        int x1 = min(x0 + 1, W - 1);
        float ly = y - (float)y0, lx = x - (float)x0;
        float hy = 1.0f - ly,     hx = 1.0f - lx;

        float sc = valid ? 0.25f : 0.0f;    // fold subsample mean + validity
        uint32_t r0 = (uint32_t)(y0 * W) * (uint32_t)C;
        uint32_t r1 = (uint32_t)(y1 * W) * (uint32_t)C;
        uint32_t c0 = (uint32_t)x0 * (uint32_t)C;
        uint32_t c1 = (uint32_t)x1 * (uint32_t)C;
        soff[tid] = make_uint4(r0 + c0, r0 + c1, r1 + c0, r1 + c1);
        swt[tid]  = make_float4(hy * hx * sc, hy * lx * sc, ly * hx * sc, ly * lx * sc);
    }
    __syncthreads();

    // ---- Phase B: 2 channels/thread, bins split across half-blocks ----
    int half = tid >> 7;                 // 0 or 1
    int c = (tid & 127) * 2;
    int bin0 = half ? 25 : 0;
    int bin1 = half ? 49 : 25;
    const float* fb = g_feat_t + (size_t)b * HW * C + c;   // even offset -> 8B aligned

    #pragma unroll 1
    for (int bin = bin0; bin < bin1; bin++) {
        float ax = 0.0f, ay = 0.0f;
        #pragma unroll
        for (int sub = 0; sub < 4; sub++) {
            int s = bin * 4 + sub;
            uint4  o = soff[s];
            float4 wv = swt[s];
            float2 v00 = __ldg((const float2*)(fb + o.x));
            float2 v01 = __ldg((const float2*)(fb + o.y));
            float2 v10 = __ldg((const float2*)(fb + o.z));
            float2 v11 = __ldg((const float2*)(fb + o.w));
            ax += wv.x * v00.x + wv.y * v01.x + wv.z * v10.x + wv.w * v11.x;
            ay += wv.x * v00.y + wv.y * v01.y + wv.z * v10.y + wv.w * v11.y;
        }
        sacc[c * (PH * PW) + bin]       = ax;
        sacc[(c + 1) * (PH * PW) + bin] = ay;
    }
    __syncthreads();

    // ---- fp16 writeout (4 halves = 8B per store) ----
    __half* outrow = g_x + (size_t)m * D;
    for (int i = tid * 4; i < D; i += 256 * 4) {
        float4 v = *(const float4*)(sacc + i);
        __half2 h0 = __floats2half2_rn(v.x, v.y);
        __half2 h1 = __floats2half2_rn(v.z, v.w);
        *(__half2*)(outrow + i)     = h0;
        *(__half2*)(outrow + i + 2) = h1;
    }
}

// ---------------- 3. FP16 mma.sync GEMM: C[M,1024] = A[M,K] @ Bt[1024,K]^T ----------------
// 128x128 CTA tile, BK=64 halves (128B/row), 8 warps (2x4), warp tile 64x32, 4-stage cp.async.
constexpr int STRH   = 72;                 // smem row stride (halves): conflict-free
constexpr int STG_H  = 2 * 128 * STRH;     // halves per stage (As + Bs)
constexpr int SMEM_GEMM = 4 * STG_H * 2;   // 147456 B

__global__ void __launch_bounds__(256) gemm_f16_kernel(
    const __half* __restrict__ A, const __half* __restrict__ Bt,
    const float* __restrict__ bias,
    float* __restrict__ CoutF, __half* __restrict__ CoutH,
    int Mi, int Ki, int flags)     // flags: bit0 relu, bit2 write fp16 (else f32)
{
    extern __shared__ __half smh[];
    int tid  = threadIdx.x;
    int wid  = tid >> 5, lane = tid & 31;
    int gq   = lane >> 2;      // groupID 0..7
    int tq   = lane & 3;       // thread-in-group 0..3
    int wm   = wid >> 2;       // 0..1  (m)
    int wn   = wid & 3;        // 0..3  (n)
    int bm   = blockIdx.y * 128;
    int bn   = blockIdx.x * 128;

    // cp.async: one thread per smem row; tid<128 -> A row, tid>=128 -> B row; 8x16B each
    int ldRow  = tid & 127;
    bool isB   = tid >= 128;
    bool ldOk  = isB || (bm + ldRow) < Mi;
    const __half* gRow = isB ? Bt + (size_t)(bn + ldRow) * Ki
                             : A  + (size_t)(bm + ldRow) * Ki;
    uint32_t sbase = smem_u32(smh);
    uint32_t sDst  = sbase + (uint32_t)((isB ? 128 + ldRow : ldRow) * STRH) * 2u;

    const int NT = Ki / 64;

    // prologue: tiles 0,1,2
    #pragma unroll
    for (int s = 0; s < 3; s++) {
        uint32_t so = (uint32_t)(s * STG_H) * 2u;
        #pragma unroll
        for (int j = 0; j < 8; j++)
            cpasync16(sDst + so + j * 16u, gRow + s * 64 + j * 8, ldOk);
        cp_commit();
    }

    float acc[4][4][4];
    #pragma unroll
    for (int i = 0; i < 4; i++)
        #pragma unroll
        for (int j = 0; j < 4; j++)
            #pragma unroll
            for (int k = 0; k < 4; k++) acc[i][j][k] = 0.0f;

    int arb = wm * 64;          // warp row base within tile
    int bcb = wn * 32;          // warp col base within tile

    for (int kt = 0; kt < NT; kt++) {
        cp_wait2();
        __syncthreads();

        // issue loads for tile kt+3 into slot (kt+3)%4
        if (kt + 3 < NT) {
            uint32_t so = (uint32_t)(((kt + 3) & 3) * STG_H) * 2u;
            const __half* p = gRow + (kt + 3) * 64;
            #pragma unroll
            for (int j = 0; j < 8; j++)
                cpasync16(sDst + so + j * 16u, p + j * 8, ldOk);
        }
        cp_commit();

        const __half* smA = smh + (kt & 3) * STG_H;
        const __half* smB = smA + 128 * STRH;

        #pragma unroll
        for (int ks = 0; ks < 4; ks++) {
            int k0 = ks * 16;
            uint32_t af[4][4], bf[4][2];
            #pragma unroll
            for (int am = 0; am < 4; am++) {
                int r = arb + am * 16 + gq;
                af[am][0] = *(const uint32_t*)(smA + r * STRH + k0 + 2 * tq);
                af[am][1] = *(const uint32_t*)(smA + (r + 8) * STRH + k0 + 2 * tq);
                af[am][2] = *(const uint32_t*)(smA + r * STRH + k0 + 8 + 2 * tq);
                af[am][3] = *(const uint32_t*)(smA + (r + 8) * STRH + k0 + 8 + 2 * tq);
            }
            #pragma unroll
            for (int bq = 0; bq < 4; bq++) {
                int n = bcb + bq * 8 + gq;
                bf[bq][0] = *(const uint32_t*)(smB + n * STRH + k0 + 2 * tq);
                bf[bq][1] = *(const uint32_t*)(smB + n * STRH + k0 + 8 + 2 * tq);
            }
            #pragma unroll
            for (int am = 0; am < 4; am++)
                #pragma unroll
                for (int bq = 0; bq < 4; bq++)
                    mma_f16(acc[am][bq], af[am], bf[bq][0], bf[bq][1]);
        }
        // no trailing __syncthreads: next iteration's top barrier provides ordering
    }

    // epilogue: bias + relu, write f32 pairs or fp16 pairs
    bool relu  = flags & 1;
    bool toH   = flags & 4;
    #pragma unroll
    for (int am = 0; am < 4; am++) {
        int r0 = bm + arb + am * 16 + gq;
        #pragma unroll
        for (int bq = 0; bq < 4; bq++) {
            int cidx = bn + bcb + bq * 8 + tq * 2;
            float b0 = bias[cidx], b1 = bias[cidx + 1];
            #pragma unroll
            for (int half = 0; half < 2; half++) {
                int row = r0 + half * 8;
                if (row < Mi) {
                    float a0 = acc[am][bq][half * 2 + 0] + b0;
                    float a1 = acc[am][bq][half * 2 + 1] + b1;
                    if (relu) { a0 = fmaxf(a0, 0.f); a1 = fmaxf(a1, 0.f); }
                    if (toH) {
                        *(__half2*)(CoutH + (size_t)row * 1024 + cidx) =
                            __floats2half2_rn(a0, a1);
                    } else {
                        *(float2*)(CoutF + (size_t)row * 1024 + cidx) =
                            make_float2(a0, a1);
                    }
                }
            }
        }
    }
}

// ---------------- 4. head: cls (11) + reg (5) ----------------
__global__ void __launch_bounds__(128) head_kernel(
    const float* __restrict__ wc, const float* __restrict__ bc,
    const float* __restrict__ wr, const float* __restrict__ br,
    float* __restrict__ out)
{
    int m = blockIdx.x;
    __shared__ float sx[OUT];
    const float* row = g_h2 + (size_t)m * OUT;
    for (int i = threadIdx.x; i < OUT; i += 128) sx[i] = row[i];
    __syncthreads();

    int o = threadIdx.x >> 3;   // 0..15
    int g = threadIdx.x & 7;
    float acc = 0.0f;
    if (o < NCLS) {
        for (int k = g; k < OUT; k += 8) acc += sx[k] * wc[(size_t)k * NCLS + o];
    } else {
        int oo = o - NCLS;
        for (int k = g; k < OUT; k += 8) acc += sx[k] * wr[(size_t)k * NREG + oo];
    }
    acc += __shfl_down_sync(0xffffffffu, acc, 4, 8);
    acc += __shfl_down_sync(0xffffffffu, acc, 2, 8);
    acc += __shfl_down_sync(0xffffffffu, acc, 1, 8);
    if (g == 0) {
        if (o < NCLS) out[(size_t)m * NCLS + o] = acc + bc[o];
        else out[(size_t)M * NCLS + (size_t)m * NREG + (o - NCLS)] = acc + br[o - NCLS];
    }
}

// ---------------- launch ----------------
extern "C" void kernel_launch(void* const* d_in, const int* in_sizes, int n_in,
                              void* d_out, int out_size)
{
    const float* feat = (const float*)d_in[0];
    const float* rois = (const float*)d_in[1];
    const float* w1   = (const float*)d_in[2];
    const float* b1   = (const float*)d_in[3];
    const float* w2   = (const float*)d_in[4];
    const float* b2   = (const float*)d_in[5];
    const float* wc   = (const float*)d_in[6];
    const float* bc   = (const float*)d_in[7];
    const float* wr   = (const float*)d_in[8];
    const float* br   = (const float*)d_in[9];
    float* out = (float*)d_out;

    float *featT, *h2;
    __half *xbuf, *w1t, *w2t, *h1;
    cudaGetSymbolAddress((void**)&featT, g_feat_t);
    cudaGetSymbolAddress((void**)&xbuf,  g_x);
    cudaGetSymbolAddress((void**)&w1t,   g_w1t);
    cudaGetSymbolAddress((void**)&w2t,   g_w2t);
    cudaGetSymbolAddress((void**)&h1,    g_h1);
    cudaGetSymbolAddress((void**)&h2,    g_h2);

    // 1. transposes: feat (f32), weights (f32 -> f16 transposed [N,K])
    {
        dim3 blk(32, 8);
        transpose_f32<<<dim3(HW / 32, C / 32, B), blk>>>(feat, featT, C, HW);
        transpose_f16<<<dim3(OUT / 32, D / 32, 1), blk>>>(w1, w1t, D, OUT);
        transpose_f16<<<dim3(OUT / 32, OUT / 32, 1), blk>>>(w2, w2t, OUT, OUT);
    }

    // 2. roi align (fp16 output)
    {
        cudaFuncSetAttribute(roi_align_kernel,
                             cudaFuncAttributeMaxDynamicSharedMemorySize, ROI_SMEM);
        roi_align_kernel<<<M, 256, ROI_SMEM>>>(rois);
    }

    // 3. fc1 + fc2 on fp16 mma.sync tensor cores (fp32 accumulate)
    cudaFuncSetAttribute(gemm_f16_kernel,
                         cudaFuncAttributeMaxDynamicSharedMemorySize, SMEM_GEMM);
    {
        dim3 grid(OUT / 128, (M + 127) / 128);   // (8, 16)
        // fc1: relu, fp16 out
        gemm_f16_kernel<<<grid, 256, SMEM_GEMM>>>(xbuf, w1t, b1, nullptr, h1, M, D, 1 | 4);
        // fc2: relu, f32 out
        gemm_f16_kernel<<<grid, 256, SMEM_GEMM>>>(h1, w2t, b2, h2, nullptr, M, OUT, 1);
    }

    // 4. heads
    head_kernel<<<M, 128>>>(wc, bc, wr, br, out);
}

// round 14
// speedup vs baseline: 1.5147x; 1.0351x over previous
#include <cuda_runtime.h>
#include <cuda_fp16.h>
#include <cstddef>
#include <cstdint>

// ---------------- problem constants ----------------
constexpr int B      = 2;
constexpr int C      = 256;
constexpr int H      = 256;
constexpr int W      = 256;
constexpr int NROI   = 1000;
constexpr int PH     = 7;
constexpr int PW     = 7;
constexpr int OUT    = 1024;
constexpr int NCLS   = 11;    // NUM_CLASSES + 1
constexpr int NREG   = 5;
constexpr int D      = C * PH * PW;   // 12544
constexpr int M      = B * NROI;      // 2000
constexpr int HW     = H * W;
constexpr int NSAMP  = PH * PW * 4;   // 196

// ---------------- scratch (static device globals; no allocation) ----------------
__device__ float  g_feat_t[(size_t)B * HW * C];   // [B, H, W, C]  f32
__device__ __half g_x[(size_t)M * D];             // aligned features (fp16)
__device__ __half g_w1t[(size_t)OUT * D];         // w1 transposed [N,K] fp16
__device__ __half g_w2t[(size_t)OUT * OUT];       // w2 transposed fp16
__device__ __half g_h1[(size_t)M * OUT];          // fc1 output fp16
__device__ float  g_h2[(size_t)M * OUT];          // fc2 output f32

// ---------------- helpers ----------------
__device__ __forceinline__ uint32_t smem_u32(const void* p) {
    uint32_t a;
    asm("{ .reg .u64 t; cvta.to.shared.u64 t, %1; cvt.u32.u64 %0, t; }" : "=r"(a) : "l"(p));
    return a;
}
__device__ __forceinline__ void cpasync16(uint32_t s, const void* g, bool pred) {
    int sz = pred ? 16 : 0;
    asm volatile("cp.async.cg.shared.global [%0], [%1], 16, %2;"
                 :: "r"(s), "l"(g), "r"(sz) : "memory");
}
__device__ __forceinline__ void cp_commit() {
    asm volatile("cp.async.commit_group;" ::: "memory");
}
__device__ __forceinline__ void cp_wait2() {
    asm volatile("cp.async.wait_group 2;" ::: "memory");
}
__device__ __forceinline__ void mma_f16(float* d, const uint32_t* a, uint32_t b0, uint32_t b1) {
    asm volatile(
        "mma.sync.aligned.m16n8k16.row.col.f32.f16.f16.f32 "
        "{%0,%1,%2,%3}, {%4,%5,%6,%7}, {%8,%9}, {%0,%1,%2,%3};"
        : "+f"(d[0]), "+f"(d[1]), "+f"(d[2]), "+f"(d[3])
        : "r"(a[0]), "r"(a[1]), "r"(a[2]), "r"(a[3]), "r"(b0), "r"(b1));
}

// ---------------- 1a. transpose f32->f32: in[z][R][Cc] -> out[z][Cc][R] ----------------
__global__ void transpose_f32(const float* __restrict__ in, float* __restrict__ out,
                              int R, int Cc) {
    __shared__ float tile[32][33];
    size_t zo = (size_t)blockIdx.z * R * Cc;
    int c0 = blockIdx.x * 32;
    int r0 = blockIdx.y * 32;
    int tx = threadIdx.x, ty = threadIdx.y;
    #pragma unroll
    for (int i = 0; i < 32; i += 8)
        tile[ty + i][tx] = in[zo + (size_t)(r0 + ty + i) * Cc + c0 + tx];
    __syncthreads();
    #pragma unroll
    for (int i = 0; i < 32; i += 8)
        out[zo + (size_t)(c0 + ty + i) * R + r0 + tx] = tile[tx][ty + i];
}

// ---------------- 1b. transpose f32->f16 ----------------
__global__ void transpose_f16(const float* __restrict__ in, __half* __restrict__ out,
                              int R, int Cc) {
    __shared__ float tile[32][33];
    int c0 = blockIdx.x * 32;
    int r0 = blockIdx.y * 32;
    int tx = threadIdx.x, ty = threadIdx.y;
    #pragma unroll
    for (int i = 0; i < 32; i += 8)
        tile[ty + i][tx] = in[(size_t)(r0 + ty + i) * Cc + c0 + tx];
    __syncthreads();
    #pragma unroll
    for (int i = 0; i < 32; i += 8)
        out[(size_t)(c0 + ty + i) * R + r0 + tx] = __float2half_rn(tile[tx][ty + i]);
}

// ---------------- 2. rotated RoI align: geometry + float4 gather, bin-quarter split ----------------
// 256 threads: quarter q = tid>>6 handles a bin range; thread owns 4 channels (LDG.128)
constexpr int ROI_SMEM = D * 4 + NSAMP * 32;   // 56448 B

__global__ void __launch_bounds__(256) roi_align_kernel(const float* __restrict__ rois) {
    extern __shared__ float sacc[];                       // [D]
    uint4*  soff = (uint4*)(sacc + D);                    // [NSAMP]
    float4* swt  = (float4*)(soff + NSAMP);               // [NSAMP]

    int m = blockIdx.x;
    int b = m / NROI;
    int tid = threadIdx.x;

    // ---- Phase A: geometry, 196 samples on first 196 threads ----
    if (tid < NSAMP) {
        const float* rp = rois + (size_t)m * 5;
        float cx = rp[0], cy = rp[1], w = rp[2], h = rp[3], th = rp[4];
        float cosT = cosf(th), sinT = sinf(th);
        float bin_h = h * (1.0f / PH);
        float bin_w = w * (1.0f / PW);

        int bin = tid >> 2;          // 0..48
        int sub = tid & 3;           // 0..3
        int ph  = bin / PW;
        int pw  = bin % PW;
        int sy  = sub >> 1;
        int sx  = sub & 1;

        float yy = -h * 0.5f + ((float)ph + (sy + 0.5f) * 0.5f) * bin_h;
        float xx = -w * 0.5f + ((float)pw + (sx + 0.5f) * 0.5f) * bin_w;
        float xs = cx + xx * cosT - yy * sinT;
        float ys = cy + xx * sinT + yy * cosT;
        bool valid = (ys > -1.0f) && (ys < (float)H) &&
                     (xs > -1.0f) && (xs < (float)W);
        float y = fminf(fmaxf(ys, 0.0f), (float)(H - 1));
        float x = fminf(fmaxf(xs, 0.0f), (float)(W - 1));
        int y0 = (int)floorf(y);
        int x0 = (int)floorf(x);
        int y1 = min(y0 + 1, H - 1);
        int x1 = min(x0 + 1, W - 1);
        float ly = y - (float)y0, lx = x - (float)x0;
        float hy = 1.0f - ly,     hx = 1.0f - lx;

        float sc = valid ? 0.25f : 0.0f;    // fold subsample mean + validity
        uint32_t r0 = (uint32_t)(y0 * W) * (uint32_t)C;
        uint32_t r1 = (uint32_t)(y1 * W) * (uint32_t)C;
        uint32_t c0 = (uint32_t)x0 * (uint32_t)C;
        uint32_t c1 = (uint32_t)x1 * (uint32_t)C;
        soff[tid] = make_uint4(r0 + c0, r0 + c1, r1 + c0, r1 + c1);
        swt[tid]  = make_float4(hy * hx * sc, hy * lx * sc, ly * hx * sc, ly * lx * sc);
    }
    __syncthreads();

    // ---- Phase B: 4 channels/thread (float4), bins split across quarter-blocks ----
    int q = tid >> 6;                    // 0..3
    int c = (tid & 63) * 4;              // channel base, 16B aligned in feat row
    // bin ranges: 13,12,12,12
    int bin0 = (q == 0) ? 0 : 13 + (q - 1) * 12;
    int bin1 = (q == 0) ? 13 : bin0 + 12;
    const float* fb = g_feat_t + (size_t)b * HW * C + c;

    #pragma unroll 1
    for (int bin = bin0; bin < bin1; bin++) {
        float a0 = 0.f, a1 = 0.f, a2 = 0.f, a3 = 0.f;
        #pragma unroll
        for (int sub = 0; sub < 4; sub++) {
            int s = bin * 4 + sub;
            uint4  o = soff[s];
            float4 wv = swt[s];
            float4 v00 = __ldg((const float4*)(fb + o.x));
            float4 v01 = __ldg((const float4*)(fb + o.y));
            float4 v10 = __ldg((const float4*)(fb + o.z));
            float4 v11 = __ldg((const float4*)(fb + o.w));
            a0 += wv.x * v00.x + wv.y * v01.x + wv.z * v10.x + wv.w * v11.x;
            a1 += wv.x * v00.y + wv.y * v01.y + wv.z * v10.y + wv.w * v11.y;
            a2 += wv.x * v00.z + wv.y * v01.z + wv.z * v10.z + wv.w * v11.z;
            a3 += wv.x * v00.w + wv.y * v01.w + wv.z * v10.w + wv.w * v11.w;
        }
        sacc[(c + 0) * (PH * PW) + bin] = a0;
        sacc[(c + 1) * (PH * PW) + bin] = a1;
        sacc[(c + 2) * (PH * PW) + bin] = a2;
        sacc[(c + 3) * (PH * PW) + bin] = a3;
    }
    __syncthreads();

    // ---- fp16 writeout (4 halves = 8B per store) ----
    __half* outrow = g_x + (size_t)m * D;
    for (int i = tid * 4; i < D; i += 256 * 4) {
        float4 v = *(const float4*)(sacc + i);
        __half2 h0 = __floats2half2_rn(v.x, v.y);
        __half2 h1 = __floats2half2_rn(v.z, v.w);
        *(__half2*)(outrow + i)     = h0;
        *(__half2*)(outrow + i + 2) = h1;
    }
}

// ---------------- 3. FP16 mma.sync GEMM: C[M,1024] = A[M,K] @ Bt[1024,K]^T ----------------
// 128x128 CTA tile, BK=64 halves (128B/row), 8 warps (2x4), warp tile 64x32, 4-stage cp.async.
constexpr int STRH   = 72;                 // smem row stride (halves): conflict-free
constexpr int STG_H  = 2 * 128 * STRH;     // halves per stage (As + Bs)
constexpr int SMEM_GEMM = 4 * STG_H * 2;   // 147456 B

__global__ void __launch_bounds__(256) gemm_f16_kernel(
    const __half* __restrict__ A, const __half* __restrict__ Bt,
    const float* __restrict__ bias,
    float* __restrict__ CoutF, __half* __restrict__ CoutH,
    int Mi, int Ki, int flags)     // flags: bit0 relu, bit2 write fp16 (else f32)
{
    extern __shared__ __half smh[];
    int tid  = threadIdx.x;
    int wid  = tid >> 5, lane = tid & 31;
    int gq   = lane >> 2;      // groupID 0..7
    int tq   = lane & 3;       // thread-in-group 0..3
    int wm   = wid >> 2;       // 0..1  (m)
    int wn   = wid & 3;        // 0..3  (n)
    int bm   = blockIdx.y * 128;
    int bn   = blockIdx.x * 128;

    // cp.async: one thread per smem row; tid<128 -> A row, tid>=128 -> B row; 8x16B each
    int ldRow  = tid & 127;
    bool isB   = tid >= 128;
    bool ldOk  = isB || (bm + ldRow) < Mi;
    const __half* gRow = isB ? Bt + (size_t)(bn + ldRow) * Ki
                             : A  + (size_t)(bm + ldRow) * Ki;
    uint32_t sbase = smem_u32(smh);
    uint32_t sDst  = sbase + (uint32_t)((isB ? 128 + ldRow : ldRow) * STRH) * 2u;

    const int NT = Ki / 64;

    // prologue: tiles 0,1,2
    #pragma unroll
    for (int s = 0; s < 3; s++) {
        uint32_t so = (uint32_t)(s * STG_H) * 2u;
        #pragma unroll
        for (int j = 0; j < 8; j++)
            cpasync16(sDst + so + j * 16u, gRow + s * 64 + j * 8, ldOk);
        cp_commit();
    }

    float acc[4][4][4];
    #pragma unroll
    for (int i = 0; i < 4; i++)
        #pragma unroll
        for (int j = 0; j < 4; j++)
            #pragma unroll
            for (int k = 0; k < 4; k++) acc[i][j][k] = 0.0f;

    int arb = wm * 64;          // warp row base within tile
    int bcb = wn * 32;          // warp col base within tile

    for (int kt = 0; kt < NT; kt++) {
        cp_wait2();
        __syncthreads();

        // issue loads for tile kt+3 into slot (kt+3)%4
        if (kt + 3 < NT) {
            uint32_t so = (uint32_t)(((kt + 3) & 3) * STG_H) * 2u;
            const __half* p = gRow + (kt + 3) * 64;
            #pragma unroll
            for (int j = 0; j < 8; j++)
                cpasync16(sDst + so + j * 16u, p + j * 8, ldOk);
        }
        cp_commit();

        const __half* smA = smh + (kt & 3) * STG_H;
        const __half* smB = smA + 128 * STRH;

        #pragma unroll
        for (int ks = 0; ks < 4; ks++) {
            int k0 = ks * 16;
            uint32_t af[4][4], bf[4][2];
            #pragma unroll
            for (int am = 0; am < 4; am++) {
                int r = arb + am * 16 + gq;
                af[am][0] = *(const uint32_t*)(smA + r * STRH + k0 + 2 * tq);
                af[am][1] = *(const uint32_t*)(smA + (r + 8) * STRH + k0 + 2 * tq);
                af[am][2] = *(const uint32_t*)(smA + r * STRH + k0 + 8 + 2 * tq);
                af[am][3] = *(const uint32_t*)(smA + (r + 8) * STRH + k0 + 8 + 2 * tq);
            }
            #pragma unroll
            for (int bq = 0; bq < 4; bq++) {
                int n = bcb + bq * 8 + gq;
                bf[bq][0] = *(const uint32_t*)(smB + n * STRH + k0 + 2 * tq);
                bf[bq][1] = *(const uint32_t*)(smB + n * STRH + k0 + 8 + 2 * tq);
            }
            #pragma unroll
            for (int am = 0; am < 4; am++)
                #pragma unroll
                for (int bq = 0; bq < 4; bq++)
                    mma_f16(acc[am][bq], af[am], bf[bq][0], bf[bq][1]);
        }
        // no trailing __syncthreads: next iteration's top barrier provides ordering
    }

    // epilogue: bias + relu, write f32 pairs or fp16 pairs
    bool relu  = flags & 1;
    bool toH   = flags & 4;
    #pragma unroll
    for (int am = 0; am < 4; am++) {
        int r0 = bm + arb + am * 16 + gq;
        #pragma unroll
        for (int bq = 0; bq < 4; bq++) {
            int cidx = bn + bcb + bq * 8 + tq * 2;
            float b0 = bias[cidx], b1 = bias[cidx + 1];
            #pragma unroll
            for (int half = 0; half < 2; half++) {
                int row = r0 + half * 8;
                if (row < Mi) {
                    float a0 = acc[am][bq][half * 2 + 0] + b0;
                    float a1 = acc[am][bq][half * 2 + 1] + b1;
                    if (relu) { a0 = fmaxf(a0, 0.f); a1 = fmaxf(a1, 0.f); }
                    if (toH) {
                        *(__half2*)(CoutH + (size_t)row * 1024 + cidx) =
                            __floats2half2_rn(a0, a1);
                    } else {
                        *(float2*)(CoutF + (size_t)row * 1024 + cidx) =
                            make_float2(a0, a1);
                    }
                }
            }
        }
    }
}

// ---------------- 4. head: cls (11) + reg (5) ----------------
__global__ void __launch_bounds__(128) head_kernel(
    const float* __restrict__ wc, const float* __restrict__ bc,
    const float* __restrict__ wr, const float* __restrict__ br,
    float* __restrict__ out)
{
    int m = blockIdx.x;
    __shared__ float sx[OUT];
    const float* row = g_h2 + (size_t)m * OUT;
    for (int i = threadIdx.x; i < OUT; i += 128) sx[i] = row[i];
    __syncthreads();

    int o = threadIdx.x >> 3;   // 0..15
    int g = threadIdx.x & 7;
    float acc = 0.0f;
    if (o < NCLS) {
        for (int k = g; k < OUT; k += 8) acc += sx[k] * wc[(size_t)k * NCLS + o];
    } else {
        int oo = o - NCLS;
        for (int k = g; k < OUT; k += 8) acc += sx[k] * wr[(size_t)k * NREG + oo];
    }
    acc += __shfl_down_sync(0xffffffffu, acc, 4, 8);
    acc += __shfl_down_sync(0xffffffffu, acc, 2, 8);
    acc += __shfl_down_sync(0xffffffffu, acc, 1, 8);
    if (g == 0) {
        if (o < NCLS) out[(size_t)m * NCLS + o] = acc + bc[o];
        else out[(size_t)M * NCLS + (size_t)m * NREG + (o - NCLS)] = acc + br[o - NCLS];
    }
}

// ---------------- launch ----------------
extern "C" void kernel_launch(void* const* d_in, const int* in_sizes, int n_in,
                              void* d_out, int out_size)
{
    const float* feat = (const float*)d_in[0];
    const float* rois = (const float*)d_in[1];
    const float* w1   = (const float*)d_in[2];
    const float* b1   = (const float*)d_in[3];
    const float* w2   = (const float*)d_in[4];
    const float* b2   = (const float*)d_in[5];
    const float* wc   = (const float*)d_in[6];
    const float* bc   = (const float*)d_in[7];
    const float* wr   = (const float*)d_in[8];
    const float* br   = (const float*)d_in[9];
    float* out = (float*)d_out;

    float *featT, *h2;
    __half *xbuf, *w1t, *w2t, *h1;
    cudaGetSymbolAddress((void**)&featT, g_feat_t);
    cudaGetSymbolAddress((void**)&xbuf,  g_x);
    cudaGetSymbolAddress((void**)&w1t,   g_w1t);
    cudaGetSymbolAddress((void**)&w2t,   g_w2t);
    cudaGetSymbolAddress((void**)&h1,    g_h1);
    cudaGetSymbolAddress((void**)&h2,    g_h2);

    // 1. transposes: feat (f32), weights (f32 -> f16 transposed [N,K])
    {
        dim3 blk(32, 8);
        transpose_f32<<<dim3(HW / 32, C / 32, B), blk>>>(feat, featT, C, HW);
        transpose_f16<<<dim3(OUT / 32, D / 32, 1), blk>>>(w1, w1t, D, OUT);
        transpose_f16<<<dim3(OUT / 32, OUT / 32, 1), blk>>>(w2, w2t, OUT, OUT);
    }

    // 2. roi align (fp16 output)
    {
        cudaFuncSetAttribute(roi_align_kernel,
                             cudaFuncAttributeMaxDynamicSharedMemorySize, ROI_SMEM);
        roi_align_kernel<<<M, 256, ROI_SMEM>>>(rois);
    }

    // 3. fc1 + fc2 on fp16 mma.sync tensor cores (fp32 accumulate)
    cudaFuncSetAttribute(gemm_f16_kernel,
                         cudaFuncAttributeMaxDynamicSharedMemorySize, SMEM_GEMM);
    {
        dim3 grid(OUT / 128, (M + 127) / 128);   // (8, 16)
        // fc1: relu, fp16 out
        gemm_f16_kernel<<<grid, 256, SMEM_GEMM>>>(xbuf, w1t, b1, nullptr, h1, M, D, 1 | 4);
        // fc2: relu, f32 out
        gemm_f16_kernel<<<grid, 256, SMEM_GEMM>>>(h1, w2t, b2, h2, nullptr, M, OUT, 1);
    }

    // 4. heads
    head_kernel<<<M, 128>>>(wc, bc, wr, br, out);
}

// round 17
// speedup vs baseline: 1.7098x; 1.1288x over previous
#include <cuda_runtime.h>
#include <cuda_fp16.h>
#include <cstddef>
#include <cstdint>

// ---------------- problem constants ----------------
constexpr int B      = 2;
constexpr int C      = 256;
constexpr int H      = 256;
constexpr int W      = 256;
constexpr int NROI   = 1000;
constexpr int PH     = 7;
constexpr int PW     = 7;
constexpr int OUT    = 1024;
constexpr int NCLS   = 11;    // NUM_CLASSES + 1
constexpr int NREG   = 5;
constexpr int D      = C * PH * PW;   // 12544
constexpr int M      = B * NROI;      // 2000
constexpr int HW     = H * W;
constexpr int NSAMP  = PH * PW * 4;   // 196

// ---------------- scratch (static device globals; no allocation) ----------------
__device__ __half g_feat_t[(size_t)B * HW * C];   // [B, H, W, C]  fp16
__device__ __half g_x[(size_t)M * D];             // aligned features (fp16)
__device__ __half g_w1t[(size_t)OUT * D];         // w1 transposed [N,K] fp16
__device__ __half g_w2t[(size_t)OUT * OUT];       // w2 transposed fp16
__device__ __half g_h1[(size_t)M * OUT];          // fc1 output fp16
__device__ float  g_h2[(size_t)M * OUT];          // fc2 output f32

// ---------------- helpers ----------------
__device__ __forceinline__ uint32_t smem_u32(const void* p) {
    uint32_t a;
    asm("{ .reg .u64 t; cvta.to.shared.u64 t, %1; cvt.u32.u64 %0, t; }" : "=r"(a) : "l"(p));
    return a;
}
__device__ __forceinline__ void cpasync16(uint32_t s, const void* g, bool pred) {
    int sz = pred ? 16 : 0;
    asm volatile("cp.async.cg.shared.global [%0], [%1], 16, %2;"
                 :: "r"(s), "l"(g), "r"(sz) : "memory");
}
__device__ __forceinline__ void cp_commit() {
    asm volatile("cp.async.commit_group;" ::: "memory");
}
__device__ __forceinline__ void cp_wait2() {
    asm volatile("cp.async.wait_group 2;" ::: "memory");
}
__device__ __forceinline__ void mma_f16(float* d, const uint32_t* a, uint32_t b0, uint32_t b1) {
    asm volatile(
        "mma.sync.aligned.m16n8k16.row.col.f32.f16.f16.f32 "
        "{%0,%1,%2,%3}, {%4,%5,%6,%7}, {%8,%9}, {%0,%1,%2,%3};"
        : "+f"(d[0]), "+f"(d[1]), "+f"(d[2]), "+f"(d[3])
        : "r"(a[0]), "r"(a[1]), "r"(a[2]), "r"(a[3]), "r"(b0), "r"(b1));
}

// ---------------- 1. transpose f32 -> f16 (batched): in[z][R][Cc] -> out[z][Cc][R] ----------------
__global__ void transpose_f16z(const float* __restrict__ in, __half* __restrict__ out,
                               int R, int Cc) {
    __shared__ float tile[32][33];
    size_t zo = (size_t)blockIdx.z * R * Cc;
    int c0 = blockIdx.x * 32;
    int r0 = blockIdx.y * 32;
    int tx = threadIdx.x, ty = threadIdx.y;
    #pragma unroll
    for (int i = 0; i < 32; i += 8)
        tile[ty + i][tx] = in[zo + (size_t)(r0 + ty + i) * Cc + c0 + tx];
    __syncthreads();
    #pragma unroll
    for (int i = 0; i < 32; i += 8)
        out[zo + (size_t)(c0 + ty + i) * R + r0 + tx] = __float2half_rn(tile[tx][ty + i]);
}

// ---------------- 2. rotated RoI align: geometry + fp16x4 gather, bin-quarter split ----------------
// 256 threads: quarter q = tid>>6 handles a bin range; thread owns 4 channels (8B loads)
constexpr int ROI_SMEM = D * 4 + NSAMP * 32;   // 56448 B

__global__ void __launch_bounds__(256) roi_align_kernel(const float* __restrict__ rois) {
    extern __shared__ float sacc[];                       // [D]
    uint4*  soff = (uint4*)(sacc + D);                    // [NSAMP]
    float4* swt  = (float4*)(soff + NSAMP);               // [NSAMP]

    int m = blockIdx.x;
    int b = m / NROI;
    int tid = threadIdx.x;

    // ---- Phase A: geometry, 196 samples on first 196 threads ----
    if (tid < NSAMP) {
        const float* rp = rois + (size_t)m * 5;
        float cx = rp[0], cy = rp[1], w = rp[2], h = rp[3], th = rp[4];
        float cosT = cosf(th), sinT = sinf(th);
        float bin_h = h * (1.0f / PH);
        float bin_w = w * (1.0f / PW);

        int bin = tid >> 2;          // 0..48
        int sub = tid & 3;           // 0..3
        int ph  = bin / PW;
        int pw  = bin % PW;
        int sy  = sub >> 1;
        int sx  = sub & 1;

        float yy = -h * 0.5f + ((float)ph + (sy + 0.5f) * 0.5f) * bin_h;
        float xx = -w * 0.5f + ((float)pw + (sx + 0.5f) * 0.5f) * bin_w;
        float xs = cx + xx * cosT - yy * sinT;
        float ys = cy + xx * sinT + yy * cosT;
        bool valid = (ys > -1.0f) && (ys < (float)H) &&
                     (xs > -1.0f) && (xs < (float)W);
        float y = fminf(fmaxf(ys, 0.0f), (float)(H - 1));
        float x = fminf(fmaxf(xs, 0.0f), (float)(W - 1));
        int y0 = (int)floorf(y);
        int x0 = (int)floorf(x);
        int y1 = min(y0 + 1, H - 1);
        int x1 = min(x0 + 1, W - 1);
        float ly = y - (float)y0, lx = x - (float)x0;
        float hy = 1.0f - ly,     hx = 1.0f - lx;

        float sc = valid ? 0.25f : 0.0f;    // fold subsample mean + validity
        uint32_t r0 = (uint32_t)(y0 * W) * (uint32_t)C;
        uint32_t r1 = (uint32_t)(y1 * W) * (uint32_t)C;
        uint32_t c0 = (uint32_t)x0 * (uint32_t)C;
        uint32_t c1 = (uint32_t)x1 * (uint32_t)C;
        soff[tid] = make_uint4(r0 + c0, r0 + c1, r1 + c0, r1 + c1);
        swt[tid]  = make_float4(hy * hx * sc, hy * lx * sc, ly * hx * sc, ly * lx * sc);
    }
    __syncthreads();

    // ---- Phase B: 4 channels/thread (2x half2 = 8B loads), bins split across quarters ----
    int q = tid >> 6;                    // 0..3
    int c = (tid & 63) * 4;              // channel base, 8B aligned in fp16 feat row
    int bin0 = (q == 0) ? 0 : 13 + (q - 1) * 12;
    int bin1 = (q == 0) ? 13 : bin0 + 12;
    const __half* fb = g_feat_t + (size_t)b * HW * C + c;

    #pragma unroll 1
    for (int bin = bin0; bin < bin1; bin++) {
        float a0 = 0.f, a1 = 0.f, a2 = 0.f, a3 = 0.f;
        #pragma unroll
        for (int sub = 0; sub < 4; sub++) {
            int s = bin * 4 + sub;
            uint4  o = soff[s];
            float4 wv = swt[s];
            #pragma unroll
            for (int corner = 0; corner < 4; corner++) {
                uint32_t off = corner == 0 ? o.x : corner == 1 ? o.y :
                               corner == 2 ? o.z : o.w;
                float wgt = corner == 0 ? wv.x : corner == 1 ? wv.y :
                            corner == 2 ? wv.z : wv.w;
                uint2 raw = __ldg((const uint2*)(fb + off));
                __half2 h01 = *(__half2*)&raw.x;
                __half2 h23 = *(__half2*)&raw.y;
                float2 f01 = __half22float2(h01);
                float2 f23 = __half22float2(h23);
                a0 += wgt * f01.x;
                a1 += wgt * f01.y;
                a2 += wgt * f23.x;
                a3 += wgt * f23.y;
            }
        }
        sacc[(c + 0) * (PH * PW) + bin] = a0;
        sacc[(c + 1) * (PH * PW) + bin] = a1;
        sacc[(c + 2) * (PH * PW) + bin] = a2;
        sacc[(c + 3) * (PH * PW) + bin] = a3;
    }
    __syncthreads();

    // ---- fp16 writeout (4 halves = 8B per store) ----
    __half* outrow = g_x + (size_t)m * D;
    for (int i = tid * 4; i < D; i += 256 * 4) {
        float4 v = *(const float4*)(sacc + i);
        __half2 h0 = __floats2half2_rn(v.x, v.y);
        __half2 h1 = __floats2half2_rn(v.z, v.w);
        *(__half2*)(outrow + i)     = h0;
        *(__half2*)(outrow + i + 2) = h1;
    }
}

// ---------------- 3. FP16 mma.sync GEMM: C[M,1024] = A[M,K] @ Bt[1024,K]^T ----------------
// 128x128 CTA tile, BK=64 halves (128B/row), 8 warps (2x4), warp tile 64x32, 4-stage cp.async.
constexpr int STRH   = 72;                 // smem row stride (halves): conflict-free
constexpr int STG_H  = 2 * 128 * STRH;     // halves per stage (As + Bs)
constexpr int SMEM_GEMM = 4 * STG_H * 2;   // 147456 B

__global__ void __launch_bounds__(256) gemm_f16_kernel(
    const __half* __restrict__ A, const __half* __restrict__ Bt,
    const float* __restrict__ bias,
    float* __restrict__ CoutF, __half* __restrict__ CoutH,
    int Mi, int Ki, int flags)     // flags: bit0 relu, bit2 write fp16 (else f32)
{
    extern __shared__ __half smh[];
    int tid  = threadIdx.x;
    int wid  = tid >> 5, lane = tid & 31;
    int gq   = lane >> 2;      // groupID 0..7
    int tq   = lane & 3;       // thread-in-group 0..3
    int wm   = wid >> 2;       // 0..1  (m)
    int wn   = wid & 3;        // 0..3  (n)
    int bm   = blockIdx.y * 128;
    int bn   = blockIdx.x * 128;

    // cp.async: one thread per smem row; tid<128 -> A row, tid>=128 -> B row; 8x16B each
    int ldRow  = tid & 127;
    bool isB   = tid >= 128;
    bool ldOk  = isB || (bm + ldRow) < Mi;
    const __half* gRow = isB ? Bt + (size_t)(bn + ldRow) * Ki
                             : A  + (size_t)(bm + ldRow) * Ki;
    uint32_t sbase = smem_u32(smh);
    uint32_t sDst  = sbase + (uint32_t)((isB ? 128 + ldRow : ldRow) * STRH) * 2u;

    const int NT = Ki / 64;

    // prologue: tiles 0,1,2
    #pragma unroll
    for (int s = 0; s < 3; s++) {
        uint32_t so = (uint32_t)(s * STG_H) * 2u;
        #pragma unroll
        for (int j = 0; j < 8; j++)
            cpasync16(sDst + so + j * 16u, gRow + s * 64 + j * 8, ldOk);
        cp_commit();
    }

    float acc[4][4][4];
    #pragma unroll
    for (int i = 0; i < 4; i++)
        #pragma unroll
        for (int j = 0; j < 4; j++)
            #pragma unroll
            for (int k = 0; k < 4; k++) acc[i][j][k] = 0.0f;

    int arb = wm * 64;          // warp row base within tile
    int bcb = wn * 32;          // warp col base within tile

    for (int kt = 0; kt < NT; kt++) {
        cp_wait2();
        __syncthreads();

        // issue loads for tile kt+3 into slot (kt+3)%4
        if (kt + 3 < NT) {
            uint32_t so = (uint32_t)(((kt + 3) & 3) * STG_H) * 2u;
            const __half* p = gRow + (kt + 3) * 64;
            #pragma unroll
            for (int j = 0; j < 8; j++)
                cpasync16(sDst + so + j * 16u, p + j * 8, ldOk);
        }
        cp_commit();

        const __half* smA = smh + (kt & 3) * STG_H;
        const __half* smB = smA + 128 * STRH;

        #pragma unroll
        for (int ks = 0; ks < 4; ks++) {
            int k0 = ks * 16;
            uint32_t af[4][4], bf[4][2];
            #pragma unroll
            for (int am = 0; am < 4; am++) {
                int r = arb + am * 16 + gq;
                af[am][0] = *(const uint32_t*)(smA + r * STRH + k0 + 2 * tq);
                af[am][1] = *(const uint32_t*)(smA + (r + 8) * STRH + k0 + 2 * tq);
                af[am][2] = *(const uint32_t*)(smA + r * STRH + k0 + 8 + 2 * tq);
                af[am][3] = *(const uint32_t*)(smA + (r + 8) * STRH + k0 + 8 + 2 * tq);
            }
            #pragma unroll
            for (int bq = 0; bq < 4; bq++) {
                int n = bcb + bq * 8 + gq;
                bf[bq][0] = *(const uint32_t*)(smB + n * STRH + k0 + 2 * tq);
                bf[bq][1] = *(const uint32_t*)(smB + n * STRH + k0 + 8 + 2 * tq);
            }
            #pragma unroll
            for (int am = 0; am < 4; am++)
                #pragma unroll
                for (int bq = 0; bq < 4; bq++)
                    mma_f16(acc[am][bq], af[am], bf[bq][0], bf[bq][1]);
        }
        // no trailing __syncthreads: next iteration's top barrier provides ordering
    }

    // epilogue: bias + relu, write f32 pairs or fp16 pairs
    bool relu  = flags & 1;
    bool toH   = flags & 4;
    #pragma unroll
    for (int am = 0; am < 4; am++) {
        int r0 = bm + arb + am * 16 + gq;
        #pragma unroll
        for (int bq = 0; bq < 4; bq++) {
            int cidx = bn + bcb + bq * 8 + tq * 2;
            float b0 = bias[cidx], b1 = bias[cidx + 1];
            #pragma unroll
            for (int half = 0; half < 2; half++) {
                int row = r0 + half * 8;
                if (row < Mi) {
                    float a0 = acc[am][bq][half * 2 + 0] + b0;
                    float a1 = acc[am][bq][half * 2 + 1] + b1;
                    if (relu) { a0 = fmaxf(a0, 0.f); a1 = fmaxf(a1, 0.f); }
                    if (toH) {
                        *(__half2*)(CoutH + (size_t)row * 1024 + cidx) =
                            __floats2half2_rn(a0, a1);
                    } else {
                        *(float2*)(CoutF + (size_t)row * 1024 + cidx) =
                            make_float2(a0, a1);
                    }
                }
            }
        }
    }
}

// ---------------- 4. head: cls (11) + reg (5) ----------------
__global__ void __launch_bounds__(128) head_kernel(
    const float* __restrict__ wc, const float* __restrict__ bc,
    const float* __restrict__ wr, const float* __restrict__ br,
    float* __restrict__ out)
{
    int m = blockIdx.x;
    __shared__ float sx[OUT];
    const float* row = g_h2 + (size_t)m * OUT;
    for (int i = threadIdx.x; i < OUT; i += 128) sx[i] = row[i];
    __syncthreads();

    int o = threadIdx.x >> 3;   // 0..15
    int g = threadIdx.x & 7;
    float acc = 0.0f;
    if (o < NCLS) {
        for (int k = g; k < OUT; k += 8) acc += sx[k] * wc[(size_t)k * NCLS + o];
    } else {
        int oo = o - NCLS;
        for (int k = g; k < OUT; k += 8) acc += sx[k] * wr[(size_t)k * NREG + oo];
    }
    acc += __shfl_down_sync(0xffffffffu, acc, 4, 8);
    acc += __shfl_down_sync(0xffffffffu, acc, 2, 8);
    acc += __shfl_down_sync(0xffffffffu, acc, 1, 8);
    if (g == 0) {
        if (o < NCLS) out[(size_t)m * NCLS + o] = acc + bc[o];
        else out[(size_t)M * NCLS + (size_t)m * NREG + (o - NCLS)] = acc + br[o - NCLS];
    }
}

// ---------------- launch ----------------
extern "C" void kernel_launch(void* const* d_in, const int* in_sizes, int n_in,
                              void* d_out, int out_size)
{
    const float* feat = (const float*)d_in[0];
    const float* rois = (const float*)d_in[1];
    const float* w1   = (const float*)d_in[2];
    const float* b1   = (const float*)d_in[3];
    const float* w2   = (const float*)d_in[4];
    const float* b2   = (const float*)d_in[5];
    const float* wc   = (const float*)d_in[6];
    const float* bc   = (const float*)d_in[7];
    const float* wr   = (const float*)d_in[8];
    const float* br   = (const float*)d_in[9];
    float* out = (float*)d_out;

    float* h2;
    __half *featT, *xbuf, *w1t, *w2t, *h1;
    cudaGetSymbolAddress((void**)&featT, g_feat_t);
    cudaGetSymbolAddress((void**)&xbuf,  g_x);
    cudaGetSymbolAddress((void**)&w1t,   g_w1t);
    cudaGetSymbolAddress((void**)&w2t,   g_w2t);
    cudaGetSymbolAddress((void**)&h1,    g_h1);
    cudaGetSymbolAddress((void**)&h2,    g_h2);

    // 1. transposes (all f32 -> f16): feat [B,C,HW]->[B,HW,C]; w1,w2 -> [N,K]
    {
        dim3 blk(32, 8);
        transpose_f16z<<<dim3(HW / 32, C / 32, B), blk>>>(feat, featT, C, HW);
        transpose_f16z<<<dim3(OUT / 32, D / 32, 1), blk>>>(w1, w1t, D, OUT);
        transpose_f16z<<<dim3(OUT / 32, OUT / 32, 1), blk>>>(w2, w2t, OUT, OUT);
    }

    // 2. roi align (fp16 feat in, fp16 out)
    {
        cudaFuncSetAttribute(roi_align_kernel,
                             cudaFuncAttributeMaxDynamicSharedMemorySize, ROI_SMEM);
        roi_align_kernel<<<M, 256, ROI_SMEM>>>(rois);
    }

    // 3. fc1 + fc2 on fp16 mma.sync tensor cores (fp32 accumulate)
    cudaFuncSetAttribute(gemm_f16_kernel,
                         cudaFuncAttributeMaxDynamicSharedMemorySize, SMEM_GEMM);
    {
        dim3 grid(OUT / 128, (M + 127) / 128);   // (8, 16)
        // fc1: relu, fp16 out
        gemm_f16_kernel<<<grid, 256, SMEM_GEMM>>>(xbuf, w1t, b1, nullptr, h1, M, D, 1 | 4);
        // fc2: relu, f32 out
        gemm_f16_kernel<<<grid, 256, SMEM_GEMM>>>(h1, w2t, b2, h2, nullptr, M, OUT, 1);
    }

    // 4. heads
    head_kernel<<<M, 128>>>(wc, bc, wr, br, out);
}